// round 13
// baseline (speedup 1.0000x reference)
#include <cuda_runtime.h>
#include <math.h>
#include <stdint.h>

#define BATCH 65536
#define FEAT  1808

// Scratch (static device globals; no allocation in kernel_launch)
__device__ float g_feats[(size_t)BATCH * FEAT + 16];  // +16: A-tail overread pad
__device__ float g_w1r[(size_t)FEAT * 256];           // tf32-rounded W1
__device__ float g_w2r[(size_t)256 * 128];            // tf32-rounded W2
__device__ float g_h1[(size_t)BATCH * 256];
__device__ float g_h2[(size_t)BATCH * 128];

// ---------------------------------------------------------------------------
// helpers
// ---------------------------------------------------------------------------
__device__ __forceinline__ uint32_t f2tf(float f) {
    uint32_t u;
    asm("cvt.rna.tf32.f32 %0, %1;" : "=r"(u) : "f"(f));
    return u;
}
__device__ __forceinline__ float rndtf(float f) {
    return __uint_as_float(f2tf(f));
}
__device__ __forceinline__ uint32_t smem_u32(const void* p) {
    uint32_t a;
    asm("{ .reg .u64 t; cvta.to.shared.u64 t, %1; cvt.u32.u64 %0, t; }"
        : "=r"(a) : "l"(p));
    return a;
}
__device__ __forceinline__ void cp_async16(uint32_t dst, const void* src) {
    asm volatile("cp.async.cg.shared.global [%0], [%1], 16;\n"
                 :: "r"(dst), "l"(src));
}
__device__ __forceinline__ void cp_commit() {
    asm volatile("cp.async.commit_group;\n" ::: "memory");
}
__device__ __forceinline__ void cp_wait1() {
    asm volatile("cp.async.wait_group 1;\n" ::: "memory");
}
__device__ __forceinline__ void cp_wait0() {
    asm volatile("cp.async.wait_group 0;\n" ::: "memory");
}
__device__ __forceinline__ void mma_tf32(float* d, const uint32_t* a, const uint32_t* b) {
    asm volatile(
        "mma.sync.aligned.m16n8k8.row.col.f32.tf32.tf32.f32 "
        "{%0,%1,%2,%3}, {%4,%5,%6,%7}, {%8,%9}, {%0,%1,%2,%3};"
        : "+f"(d[0]), "+f"(d[1]), "+f"(d[2]), "+f"(d[3])
        : "r"(a[0]), "r"(a[1]), "r"(a[2]), "r"(a[3]), "r"(b[0]), "r"(b[1]));
}

// ---------------------------------------------------------------------------
// Weight pre-rounding (tf32-rna) into device globals
// ---------------------------------------------------------------------------
__global__ void round_copy(const float* __restrict__ src, float* __restrict__ dst, int n) {
    int i = blockIdx.x * blockDim.x + threadIdx.x;
    if (i < n) dst[i] = rndtf(src[i]);
}

// ---------------------------------------------------------------------------
// Kernel 1: features, warp/sample — writes tf32-rounded values
// ---------------------------------------------------------------------------
__global__ __launch_bounds__(256) void feat_kernel(const float* __restrict__ x) {
    int gw = (blockIdx.x * blockDim.x + threadIdx.x) >> 5;
    int lane = threadIdx.x & 31;
    if (gw >= BATCH) return;
    const float* xr = x + (size_t)gw * 512;
    float* fr = g_feats + (size_t)gw * FEAT;

    float c[16];
#pragma unroll
    for (int k = 0; k < 16; k++) c[k] = xr[k * 32 + lane];
#pragma unroll
    for (int k = 0; k < 16; k++) fr[k * 32 + lane] = rndtf(c[k]);

#pragma unroll
    for (int i = 0; i < 32; i++) {
        float acc = 0.f;
#pragma unroll
        for (int k = 0; k < 16; k++)
            acc = fmaf(__shfl_sync(0xffffffffu, c[k], i), c[k], acc);
        fr[512 + i * 32 + lane] = rndtf(acc);
    }

    float outv[8];
#pragma unroll
    for (int r = 0; r < 8; r++) outv[r] = 0.f;
#pragma unroll
    for (int i = 0; i < 16; i++) {
#pragma unroll
        for (int j = i; j < 16; j++) {
            float v = c[i] * c[j];
            v += __shfl_xor_sync(0xffffffffu, v, 16);
            v += __shfl_xor_sync(0xffffffffu, v, 8);
            v += __shfl_xor_sync(0xffffffffu, v, 4);
            v += __shfl_xor_sync(0xffffffffu, v, 2);
            v += __shfl_xor_sync(0xffffffffu, v, 1);
            int p1 = i * 16 + j;
            if (lane == (p1 & 31)) outv[p1 >> 5] = v;
            if (i != j) {
                int p2 = j * 16 + i;
                if (lane == (p2 & 31)) outv[p2 >> 5] = v;
            }
        }
    }
#pragma unroll
    for (int r = 0; r < 8; r++) fr[1536 + r * 32 + lane] = rndtf(outv[r]);
}

// ---------------------------------------------------------------------------
// Kernel 2: SVD via cyclic Jacobi on 16x16 Gram in shared memory.
// One sample/thread, 4 sweeps, 128-thread blocks, 3 blocks/SM.
// Warp-uniform convergence skip — if ALL lanes' apq^2 <= 1e-9*app*aqq
// the rotation is skipped (uniform branch, no divergence). Eigenvalue
// perturbation O(apq^2/gap) ~ 1e-9: invisible at the 1e-3 budget.
// ---------------------------------------------------------------------------
__device__ __forceinline__ constexpr int SIDX(int i, int j) {
    return i * 16 - i * (i - 1) / 2 + (j - i);
}
__device__ __forceinline__ int ROFF(int i) {
    return i * 16 - i * (i - 1) / 2 - i;
}

__global__ __launch_bounds__(128, 3) void svd_kernel() {
    extern __shared__ float sa[];
    int t = threadIdx.x;
    size_t s = (size_t)blockIdx.x * 128 + t;
    float* fr = g_feats + s * FEAT;
    float* m = sa + t * 137;

#pragma unroll
    for (int i = 0; i < 16; i++)
#pragma unroll
        for (int j = i; j < 16; j++)
            m[SIDX(i, j)] = fr[1536 + i * 16 + j];

#pragma unroll 1
    for (int sw = 0; sw < 4; sw++) {
#pragma unroll 1
        for (int p = 0; p < 15; p++) {
            int roffp = ROFF(p);
#pragma unroll 1
            for (int q = p + 1; q < 16; q++) {
                int roffq = ROFF(q);
                float apq = m[roffp + q];
                float app = m[roffp + p];
                float aqq = m[roffq + q];

                // warp-uniform convergence skip (app,aqq >= 0: PSD Gram)
                bool tiny = (apq * apq <= 1e-9f * app * aqq);
                if (__all_sync(0xffffffffu, tiny)) continue;

                float theta = __fdividef(0.5f * (aqq - app), apq);
                float tt = copysignf(1.0f, theta) /
                           (fabsf(theta) + sqrtf(fmaf(theta, theta, 1.0f)));
                tt = (apq == 0.0f) ? 0.0f : tt;
                float cth = rsqrtf(fmaf(tt, tt, 1.0f));
                float sth = tt * cth;
                m[roffp + p] = app - tt * apq;
                m[roffq + q] = aqq + tt * apq;
                m[roffp + q] = 0.f;
#pragma unroll
                for (int i = 0; i < 16; i++) {
                    int ip = (i < p) ? (ROFF(i) + p) : (roffp + i);
                    int iq = (i < q) ? (ROFF(i) + q) : (roffq + i);
                    float aip = m[ip], aiq = m[iq];
                    float n1 = cth * aip - sth * aiq;
                    float n2 = sth * aip + cth * aiq;
                    if (i != p && i != q) { m[ip] = n1; m[iq] = n2; }
                }
            }
        }
    }

    float sv[16];
#pragma unroll
    for (int i = 0; i < 16; i++) sv[i] = sqrtf(fmaxf(m[ROFF(i) + i], 0.f));

#pragma unroll
    for (int i = 0; i < 15; i++)
#pragma unroll
        for (int j = 0; j < 15 - i; j++) {
            float hi = fmaxf(sv[j], sv[j + 1]);
            float lo = fminf(sv[j], sv[j + 1]);
            sv[j] = hi;
            sv[j + 1] = lo;
        }
    float4* o = (float4*)(fr + 1792);
#pragma unroll
    for (int i = 0; i < 4; i++)
        o[i] = make_float4(rndtf(sv[i * 4]), rndtf(sv[i * 4 + 1]),
                           rndtf(sv[i * 4 + 2]), rndtf(sv[i * 4 + 3]));
}

// ---------------------------------------------------------------------------
// Pipelined TF32 GEMM: C = relu?(A @ B + bias). Inputs must be pre-rounded
// to tf32 (raw bits fed to mma). Block 128x128, warp 64x32, BK=32.
// A: cp.async 3-stage, XOR-swizzled row-major (race-safe issue ordering).
// B: register staged into bank-rotated fragment layout.
// dynamic smem: A 3*16KB + B 2*16KB = 80KB
// ---------------------------------------------------------------------------
__global__ __launch_bounds__(256, 2) void gemm_tf32_pipe(
    int M, int N, int K, int NTt,
    const float* __restrict__ A,
    const float* __restrict__ Bw,
    const float* __restrict__ bias,
    float* __restrict__ C,
    int do_relu, int do_round)
{
    extern __shared__ uint32_t sm[];
    uint32_t* Asm = sm;               // 3 stages x 4096 words
    uint32_t* Bsm = sm + 3 * 4096;    // 2 bufs x 4096 words
    uint32_t sbase = smem_u32(sm);

    int tid = threadIdx.x;
    int bx = blockIdx.x, by = blockIdx.y;
    int warp = tid >> 5, lane = tid & 31;
    int wm = warp >> 2, wn = warp & 3;

    // ---- A cp.async addressing ----
    int am = tid >> 1;                    // 0..127
    int ak0 = (tid & 1) * 16;             // 0 or 16
    int axr = 4 * (am & 7);
    uint32_t adst[4];
#pragma unroll
    for (int j = 0; j < 4; j++)
        adst[j] = (uint32_t)(am * 32 + ((ak0 + 4 * j) ^ axr)) * 4;
    const float* aptr = A + (size_t)(by * 128 + am) * K + ak0;

    // ---- B loader addressing ----
    int rowB0 = tid >> 4;                 // 0..15
    int nt0 = tid & 15;
    int colB = nt0 * 8;
    int kk = rowB0 & 7, tB = kk & 3, rB = kk >> 2, ks0 = rowB0 >> 3;
    int bb1 = nt0 * 256 + ks0 * 64 + rB * 32;
    int brot[8];
#pragma unroll
    for (int j = 0; j < 8; j++) brot[j] = (4 * j + tB + 2 * nt0) & 31;
    const float* bptr = Bw + (size_t)rowB0 * N + bx * 128 + colB;

    // ---- fragment read addressing ----
    int q = lane >> 2, t4 = lane & 3;
    int abase0 = (wm * 64 + q) * 32;
    int abase1 = abase0 + 8 * 32;
    int kx[4][2];
#pragma unroll
    for (int s = 0; s < 4; s++)
#pragma unroll
        for (int h = 0; h < 2; h++)
            kx[s][h] = t4 + 4 * (((2 * s + h) ^ q) & 7);
    int rotB[4];
#pragma unroll
    for (int nt = 0; nt < 4; nt++)
        rotB[nt] = (lane + 2 * (wn * 4 + nt)) & 31;

    float acc[4][4][4];
#pragma unroll
    for (int mt = 0; mt < 4; mt++)
#pragma unroll
        for (int nt = 0; nt < 4; nt++)
#pragma unroll
            for (int r = 0; r < 4; r++) acc[mt][nt][r] = 0.f;

    // ---- prologue ----
#pragma unroll
    for (int st = 0; st < 2; st++) {
        if (st < NTt) {
#pragma unroll
            for (int j = 0; j < 4; j++)
                cp_async16(sbase + (uint32_t)st * 16384 + adst[j],
                           aptr + (size_t)st * 32 + 4 * j);
        }
        cp_commit();
    }
    float4 bv[4];
    {
        int k2 = rowB0 + 16;
        bv[0] = *(const float4*)(bptr);
        bv[1] = *(const float4*)(bptr + 4);
        bv[2] = (k2 < K) ? *(const float4*)(bptr + (size_t)16 * N)
                         : make_float4(0.f, 0.f, 0.f, 0.f);
        bv[3] = (k2 < K) ? *(const float4*)(bptr + (size_t)16 * N + 4)
                         : make_float4(0.f, 0.f, 0.f, 0.f);
        uint32_t* bs = Bsm;
        const float* v = (const float*)bv;
#pragma unroll
        for (int j = 0; j < 8; j++) {
            bs[bb1 + brot[j]]       = __float_as_uint(v[j]);
            bs[bb1 + 128 + brot[j]] = __float_as_uint(v[j + 8]);
        }
    }

#pragma unroll 1
    for (int kt = 0; kt < NTt; kt++) {
        cp_wait1();
        __syncthreads();

        if (kt + 2 < NTt) {
#pragma unroll
            for (int j = 0; j < 4; j++)
                cp_async16(sbase + (uint32_t)((kt + 2) % 3) * 16384 + adst[j],
                           aptr + (size_t)(kt + 2) * 32 + 4 * j);
        }
        cp_commit();

        bool bnext = (kt + 1) < NTt;
        if (bnext) {
            int kb = (kt + 1) * 32;
            int k1 = kb + rowB0, k2 = k1 + 16;
            const float* bp = bptr + (size_t)kb * N;
            bv[0] = (k1 < K) ? *(const float4*)(bp)
                             : make_float4(0.f, 0.f, 0.f, 0.f);
            bv[1] = (k1 < K) ? *(const float4*)(bp + 4)
                             : make_float4(0.f, 0.f, 0.f, 0.f);
            bv[2] = (k2 < K) ? *(const float4*)(bp + (size_t)16 * N)
                             : make_float4(0.f, 0.f, 0.f, 0.f);
            bv[3] = (k2 < K) ? *(const float4*)(bp + (size_t)16 * N + 4)
                             : make_float4(0.f, 0.f, 0.f, 0.f);
        }

        const uint32_t* as = Asm + (kt % 3) * 4096;
        const uint32_t* bs = Bsm + (kt & 1) * 4096;
#pragma unroll
        for (int s = 0; s < 4; s++) {
            uint32_t af[4][4];
            uint32_t bf[4][2];
#pragma unroll
            for (int mt = 0; mt < 4; mt++) {
                int mo = mt * 512;
                af[mt][0] = as[abase0 + mo + kx[s][0]];
                af[mt][1] = as[abase1 + mo + kx[s][0]];
                af[mt][2] = as[abase0 + mo + kx[s][1]];
                af[mt][3] = as[abase1 + mo + kx[s][1]];
            }
#pragma unroll
            for (int nt = 0; nt < 4; nt++) {
                int base = (wn * 4 + nt) * 256 + s * 64;
                bf[nt][0] = bs[base + rotB[nt]];
                bf[nt][1] = bs[base + 32 + rotB[nt]];
            }
#pragma unroll
            for (int mt = 0; mt < 4; mt++)
#pragma unroll
                for (int nt = 0; nt < 4; nt++)
                    mma_tf32(acc[mt][nt], af[mt], bf[nt]);
        }

        if (bnext) {
            uint32_t* bsn = Bsm + ((kt + 1) & 1) * 4096;
            const float* v = (const float*)bv;
#pragma unroll
            for (int j = 0; j < 8; j++) {
                bsn[bb1 + brot[j]]       = __float_as_uint(v[j]);
                bsn[bb1 + 128 + brot[j]] = __float_as_uint(v[j + 8]);
            }
        }
    }
    cp_wait0();

    // epilogue
    int gc = lane >> 2, tc = lane & 3;
#pragma unroll
    for (int mt = 0; mt < 4; mt++) {
        int m0 = by * 128 + wm * 64 + mt * 16 + gc;
#pragma unroll
        for (int nt = 0; nt < 4; nt++) {
            int n = bx * 128 + wn * 32 + nt * 8 + tc * 2;
            float b0v = bias[n], b1v = bias[n + 1];
            float v0 = acc[mt][nt][0] + b0v;
            float v1 = acc[mt][nt][1] + b1v;
            float v2 = acc[mt][nt][2] + b0v;
            float v3 = acc[mt][nt][3] + b1v;
            if (do_relu) {
                v0 = fmaxf(v0, 0.f); v1 = fmaxf(v1, 0.f);
                v2 = fmaxf(v2, 0.f); v3 = fmaxf(v3, 0.f);
            }
            if (do_round) {
                v0 = rndtf(v0); v1 = rndtf(v1);
                v2 = rndtf(v2); v3 = rndtf(v3);
            }
            *(float2*)(C + (size_t)m0 * N + n)       = make_float2(v0, v1);
            *(float2*)(C + (size_t)(m0 + 8) * N + n) = make_float2(v2, v3);
        }
    }
}

// ---------------------------------------------------------------------------
// Fused layers 3+4
// ---------------------------------------------------------------------------
__global__ __launch_bounds__(256) void tail_kernel(
    const float* __restrict__ W3, const float* __restrict__ b3,
    const float* __restrict__ W4, const float* __restrict__ b4,
    float* __restrict__ out)
{
    __shared__ float sW3[128 * 64];
    __shared__ float sb3[64];
    __shared__ float sW4[64];
    int tid = threadIdx.x;
    for (int i = tid; i < 128 * 64; i += 256) sW3[i] = W3[i];
    if (tid < 64) { sb3[tid] = b3[tid]; sW4[tid] = W4[tid]; }
    __syncthreads();

    int s = blockIdx.x * 256 + tid;
    if (s >= BATCH) return;
    const float4* h2r = (const float4*)(g_h2 + (size_t)s * 128);

    float h3[64];
#pragma unroll
    for (int o = 0; o < 64; o++) h3[o] = sb3[o];

    for (int k4 = 0; k4 < 32; k4++) {
        float4 v = h2r[k4];
        float hv[4] = {v.x, v.y, v.z, v.w};
#pragma unroll
        for (int u = 0; u < 4; u++) {
            const float* wrow = &sW3[(k4 * 4 + u) * 64];
#pragma unroll
            for (int o = 0; o < 64; o++) h3[o] = fmaf(hv[u], wrow[o], h3[o]);
        }
    }
    float accv = b4[0];
#pragma unroll
    for (int o = 0; o < 64; o++) accv = fmaf(fmaxf(h3[o], 0.f), sW4[o], accv);
    out[s] = accv;
}

// ---------------------------------------------------------------------------
extern "C" void kernel_launch(void* const* d_in, const int* in_sizes, int n_in,
                              void* d_out, int out_size) {
    const float* x  = (const float*)d_in[0];
    const float* W1 = (const float*)d_in[1];
    const float* b1 = (const float*)d_in[2];
    const float* W2 = (const float*)d_in[3];
    const float* b2 = (const float*)d_in[4];
    const float* W3 = (const float*)d_in[5];
    const float* b3 = (const float*)d_in[6];
    const float* W4 = (const float*)d_in[7];
    const float* b4 = (const float*)d_in[8];
    float* out = (float*)d_out;

    float *feats, *h1, *h2, *w1r, *w2r;
    cudaGetSymbolAddress((void**)&feats, g_feats);
    cudaGetSymbolAddress((void**)&h1, g_h1);
    cudaGetSymbolAddress((void**)&h2, g_h2);
    cudaGetSymbolAddress((void**)&w1r, g_w1r);
    cudaGetSymbolAddress((void**)&w2r, g_w2r);

    cudaFuncSetAttribute(gemm_tf32_pipe,
                         cudaFuncAttributeMaxDynamicSharedMemorySize, 81920);
    cudaFuncSetAttribute(svd_kernel,
                         cudaFuncAttributeMaxDynamicSharedMemorySize, 70144);

    // weight pre-rounding
    round_copy<<<(FEAT * 256 + 255) / 256, 256>>>(W1, w1r, FEAT * 256);
    round_copy<<<(256 * 128 + 255) / 256, 256>>>(W2, w2r, 256 * 128);

    feat_kernel<<<BATCH / 8, 256>>>(x);
    svd_kernel<<<BATCH / 128, 128, 70144>>>();

    // layer 1: [B,1808] @ [1808,256] + b1, relu, round (for layer-2 input)
    {
        dim3 grid(2, BATCH / 128);
        gemm_tf32_pipe<<<grid, 256, 81920>>>(BATCH, 256, FEAT, 57,
                                             feats, w1r, b1, h1, 1, 1);
    }
    // layer 2: [B,256] @ [256,128] + b2, relu
    {
        dim3 grid(1, BATCH / 128);
        gemm_tf32_pipe<<<grid, 256, 81920>>>(BATCH, 128, 256, 8,
                                             h1, w2r, b2, h2, 1, 0);
    }
    tail_kernel<<<BATCH / 256, 256>>>(W3, b3, W4, b4, out);
}

// round 14
// speedup vs baseline: 1.1051x; 1.1051x over previous
#include <cuda_runtime.h>
#include <math.h>
#include <stdint.h>

#define BATCH 65536
#define FEAT  1808

// Scratch (static device globals; no allocation in kernel_launch)
__device__ float g_feats[(size_t)BATCH * FEAT + 16];  // +16: A-tail overread pad
__device__ float g_w1r[(size_t)FEAT * 256];           // tf32-rounded W1
__device__ float g_w2r[(size_t)256 * 128];            // tf32-rounded W2
__device__ float g_h1[(size_t)BATCH * 256];
__device__ float g_h2[(size_t)BATCH * 128];

// ---------------------------------------------------------------------------
// helpers
// ---------------------------------------------------------------------------
__device__ __forceinline__ uint32_t f2tf(float f) {
    uint32_t u;
    asm("cvt.rna.tf32.f32 %0, %1;" : "=r"(u) : "f"(f));
    return u;
}
__device__ __forceinline__ float rndtf(float f) {
    return __uint_as_float(f2tf(f));
}
__device__ __forceinline__ uint32_t smem_u32(const void* p) {
    uint32_t a;
    asm("{ .reg .u64 t; cvta.to.shared.u64 t, %1; cvt.u32.u64 %0, t; }"
        : "=r"(a) : "l"(p));
    return a;
}
__device__ __forceinline__ void cp_async16(uint32_t dst, const void* src) {
    asm volatile("cp.async.cg.shared.global [%0], [%1], 16;\n"
                 :: "r"(dst), "l"(src));
}
__device__ __forceinline__ void cp_commit() {
    asm volatile("cp.async.commit_group;\n" ::: "memory");
}
__device__ __forceinline__ void cp_wait1() {
    asm volatile("cp.async.wait_group 1;\n" ::: "memory");
}
__device__ __forceinline__ void cp_wait0() {
    asm volatile("cp.async.wait_group 0;\n" ::: "memory");
}
__device__ __forceinline__ void mma_tf32(float* d, const uint32_t* a, const uint32_t* b) {
    asm volatile(
        "mma.sync.aligned.m16n8k8.row.col.f32.tf32.tf32.f32 "
        "{%0,%1,%2,%3}, {%4,%5,%6,%7}, {%8,%9}, {%0,%1,%2,%3};"
        : "+f"(d[0]), "+f"(d[1]), "+f"(d[2]), "+f"(d[3])
        : "r"(a[0]), "r"(a[1]), "r"(a[2]), "r"(a[3]), "r"(b[0]), "r"(b[1]));
}

// ---------------------------------------------------------------------------
// Weight pre-rounding (tf32-rna) into device globals
// ---------------------------------------------------------------------------
__global__ void round_copy(const float* __restrict__ src, float* __restrict__ dst, int n) {
    int i = blockIdx.x * blockDim.x + threadIdx.x;
    if (i < n) dst[i] = rndtf(src[i]);
}

// ---------------------------------------------------------------------------
// Kernel 1: features, warp/sample — writes tf32-rounded values
// ---------------------------------------------------------------------------
__global__ __launch_bounds__(256) void feat_kernel(const float* __restrict__ x) {
    int gw = (blockIdx.x * blockDim.x + threadIdx.x) >> 5;
    int lane = threadIdx.x & 31;
    if (gw >= BATCH) return;
    const float* xr = x + (size_t)gw * 512;
    float* fr = g_feats + (size_t)gw * FEAT;

    float c[16];
#pragma unroll
    for (int k = 0; k < 16; k++) c[k] = xr[k * 32 + lane];
#pragma unroll
    for (int k = 0; k < 16; k++) fr[k * 32 + lane] = rndtf(c[k]);

#pragma unroll
    for (int i = 0; i < 32; i++) {
        float acc = 0.f;
#pragma unroll
        for (int k = 0; k < 16; k++)
            acc = fmaf(__shfl_sync(0xffffffffu, c[k], i), c[k], acc);
        fr[512 + i * 32 + lane] = rndtf(acc);
    }

    float outv[8];
#pragma unroll
    for (int r = 0; r < 8; r++) outv[r] = 0.f;
#pragma unroll
    for (int i = 0; i < 16; i++) {
#pragma unroll
        for (int j = i; j < 16; j++) {
            float v = c[i] * c[j];
            v += __shfl_xor_sync(0xffffffffu, v, 16);
            v += __shfl_xor_sync(0xffffffffu, v, 8);
            v += __shfl_xor_sync(0xffffffffu, v, 4);
            v += __shfl_xor_sync(0xffffffffu, v, 2);
            v += __shfl_xor_sync(0xffffffffu, v, 1);
            int p1 = i * 16 + j;
            if (lane == (p1 & 31)) outv[p1 >> 5] = v;
            if (i != j) {
                int p2 = j * 16 + i;
                if (lane == (p2 & 31)) outv[p2 >> 5] = v;
            }
        }
    }
#pragma unroll
    for (int r = 0; r < 8; r++) fr[1536 + r * 32 + lane] = rndtf(outv[r]);
}

// ---------------------------------------------------------------------------
// Kernel 2: SVD via cyclic Jacobi on 16x16 Gram in shared memory.
// One sample/thread, 4 sweeps, 128-thread blocks, 3 blocks/SM (round-11 best).
// ---------------------------------------------------------------------------
__device__ __forceinline__ constexpr int SIDX(int i, int j) {
    return i * 16 - i * (i - 1) / 2 + (j - i);
}
__device__ __forceinline__ int ROFF(int i) {
    return i * 16 - i * (i - 1) / 2 - i;
}

__global__ __launch_bounds__(128, 3) void svd_kernel() {
    extern __shared__ float sa[];
    int t = threadIdx.x;
    size_t s = (size_t)blockIdx.x * 128 + t;
    float* fr = g_feats + s * FEAT;
    float* m = sa + t * 137;

#pragma unroll
    for (int i = 0; i < 16; i++)
#pragma unroll
        for (int j = i; j < 16; j++)
            m[SIDX(i, j)] = fr[1536 + i * 16 + j];

#pragma unroll 1
    for (int sw = 0; sw < 4; sw++) {
#pragma unroll 1
        for (int p = 0; p < 15; p++) {
            int roffp = ROFF(p);
#pragma unroll 1
            for (int q = p + 1; q < 16; q++) {
                int roffq = ROFF(q);
                float apq = m[roffp + q];
                float app = m[roffp + p];
                float aqq = m[roffq + q];
                float theta = __fdividef(0.5f * (aqq - app), apq);
                float tt = copysignf(1.0f, theta) /
                           (fabsf(theta) + sqrtf(fmaf(theta, theta, 1.0f)));
                tt = (apq == 0.0f) ? 0.0f : tt;
                float cth = rsqrtf(fmaf(tt, tt, 1.0f));
                float sth = tt * cth;
                m[roffp + p] = app - tt * apq;
                m[roffq + q] = aqq + tt * apq;
                m[roffp + q] = 0.f;
#pragma unroll
                for (int i = 0; i < 16; i++) {
                    int ip = (i < p) ? (ROFF(i) + p) : (roffp + i);
                    int iq = (i < q) ? (ROFF(i) + q) : (roffq + i);
                    float aip = m[ip], aiq = m[iq];
                    float n1 = cth * aip - sth * aiq;
                    float n2 = sth * aip + cth * aiq;
                    if (i != p && i != q) { m[ip] = n1; m[iq] = n2; }
                }
            }
        }
    }

    float sv[16];
#pragma unroll
    for (int i = 0; i < 16; i++) sv[i] = sqrtf(fmaxf(m[ROFF(i) + i], 0.f));

#pragma unroll
    for (int i = 0; i < 15; i++)
#pragma unroll
        for (int j = 0; j < 15 - i; j++) {
            float hi = fmaxf(sv[j], sv[j + 1]);
            float lo = fminf(sv[j], sv[j + 1]);
            sv[j] = hi;
            sv[j + 1] = lo;
        }
    float4* o = (float4*)(fr + 1792);
#pragma unroll
    for (int i = 0; i < 4; i++)
        o[i] = make_float4(rndtf(sv[i * 4]), rndtf(sv[i * 4 + 1]),
                           rndtf(sv[i * 4 + 2]), rndtf(sv[i * 4 + 3]));
}

// ---------------------------------------------------------------------------
// Pipelined TF32 GEMM: C = epilogue(A @ B [+ C] [+ bias]). Inputs pre-rounded
// to tf32. Block 128x128, warp 64x32, BK=32, cp.async 3-stage A pipeline.
// Ka = A row stride; Kb = valid B rows (rows >= Kb read as zero).
// do_accum: C += partial (for K-split). do_bias/do_relu/do_round: epilogue.
// dynamic smem: A 3*16KB + B 2*16KB = 80KB
// ---------------------------------------------------------------------------
__global__ __launch_bounds__(256, 2) void gemm_tf32_pipe(
    int M, int N, int Ka, int Kb, int NTt,
    const float* __restrict__ A,
    const float* __restrict__ Bw,
    const float* __restrict__ bias,
    float* __restrict__ C,
    int do_relu, int do_round, int do_accum, int do_bias)
{
    extern __shared__ uint32_t sm[];
    uint32_t* Asm = sm;               // 3 stages x 4096 words
    uint32_t* Bsm = sm + 3 * 4096;    // 2 bufs x 4096 words
    uint32_t sbase = smem_u32(sm);

    int tid = threadIdx.x;
    int bx = blockIdx.x, by = blockIdx.y;
    int warp = tid >> 5, lane = tid & 31;
    int wm = warp >> 2, wn = warp & 3;

    // ---- A cp.async addressing ----
    int am = tid >> 1;                    // 0..127
    int ak0 = (tid & 1) * 16;             // 0 or 16
    int axr = 4 * (am & 7);
    uint32_t adst[4];
#pragma unroll
    for (int j = 0; j < 4; j++)
        adst[j] = (uint32_t)(am * 32 + ((ak0 + 4 * j) ^ axr)) * 4;
    const float* aptr = A + (size_t)(by * 128 + am) * Ka + ak0;

    // ---- B loader addressing ----
    int rowB0 = tid >> 4;                 // 0..15
    int nt0 = tid & 15;
    int colB = nt0 * 8;
    int kk = rowB0 & 7, tB = kk & 3, rB = kk >> 2, ks0 = rowB0 >> 3;
    int bb1 = nt0 * 256 + ks0 * 64 + rB * 32;
    int brot[8];
#pragma unroll
    for (int j = 0; j < 8; j++) brot[j] = (4 * j + tB + 2 * nt0) & 31;
    const float* bptr = Bw + (size_t)rowB0 * N + bx * 128 + colB;

    // ---- fragment read addressing ----
    int q = lane >> 2, t4 = lane & 3;
    int abase0 = (wm * 64 + q) * 32;
    int abase1 = abase0 + 8 * 32;
    int kx[4][2];
#pragma unroll
    for (int s = 0; s < 4; s++)
#pragma unroll
        for (int h = 0; h < 2; h++)
            kx[s][h] = t4 + 4 * (((2 * s + h) ^ q) & 7);
    int rotB[4];
#pragma unroll
    for (int nt = 0; nt < 4; nt++)
        rotB[nt] = (lane + 2 * (wn * 4 + nt)) & 31;

    float acc[4][4][4];
#pragma unroll
    for (int mt = 0; mt < 4; mt++)
#pragma unroll
        for (int nt = 0; nt < 4; nt++)
#pragma unroll
            for (int r = 0; r < 4; r++) acc[mt][nt][r] = 0.f;

    // ---- prologue ----
#pragma unroll
    for (int st = 0; st < 2; st++) {
        if (st < NTt) {
#pragma unroll
            for (int j = 0; j < 4; j++)
                cp_async16(sbase + (uint32_t)st * 16384 + adst[j],
                           aptr + (size_t)st * 32 + 4 * j);
        }
        cp_commit();
    }
    float4 bv[4];
    {
        int k2 = rowB0 + 16;
        bv[0] = *(const float4*)(bptr);
        bv[1] = *(const float4*)(bptr + 4);
        bv[2] = (k2 < Kb) ? *(const float4*)(bptr + (size_t)16 * N)
                          : make_float4(0.f, 0.f, 0.f, 0.f);
        bv[3] = (k2 < Kb) ? *(const float4*)(bptr + (size_t)16 * N + 4)
                          : make_float4(0.f, 0.f, 0.f, 0.f);
        uint32_t* bs = Bsm;
        const float* v = (const float*)bv;
#pragma unroll
        for (int j = 0; j < 8; j++) {
            bs[bb1 + brot[j]]       = __float_as_uint(v[j]);
            bs[bb1 + 128 + brot[j]] = __float_as_uint(v[j + 8]);
        }
    }

#pragma unroll 1
    for (int kt = 0; kt < NTt; kt++) {
        cp_wait1();
        __syncthreads();

        if (kt + 2 < NTt) {
#pragma unroll
            for (int j = 0; j < 4; j++)
                cp_async16(sbase + (uint32_t)((kt + 2) % 3) * 16384 + adst[j],
                           aptr + (size_t)(kt + 2) * 32 + 4 * j);
        }
        cp_commit();

        bool bnext = (kt + 1) < NTt;
        if (bnext) {
            int kb = (kt + 1) * 32;
            int k1 = kb + rowB0, k2 = k1 + 16;
            const float* bp = bptr + (size_t)kb * N;
            bv[0] = (k1 < Kb) ? *(const float4*)(bp)
                              : make_float4(0.f, 0.f, 0.f, 0.f);
            bv[1] = (k1 < Kb) ? *(const float4*)(bp + 4)
                              : make_float4(0.f, 0.f, 0.f, 0.f);
            bv[2] = (k2 < Kb) ? *(const float4*)(bp + (size_t)16 * N)
                              : make_float4(0.f, 0.f, 0.f, 0.f);
            bv[3] = (k2 < Kb) ? *(const float4*)(bp + (size_t)16 * N + 4)
                              : make_float4(0.f, 0.f, 0.f, 0.f);
        }

        const uint32_t* as = Asm + (kt % 3) * 4096;
        const uint32_t* bs = Bsm + (kt & 1) * 4096;
#pragma unroll
        for (int s = 0; s < 4; s++) {
            uint32_t af[4][4];
            uint32_t bf[4][2];
#pragma unroll
            for (int mt = 0; mt < 4; mt++) {
                int mo = mt * 512;
                af[mt][0] = as[abase0 + mo + kx[s][0]];
                af[mt][1] = as[abase1 + mo + kx[s][0]];
                af[mt][2] = as[abase0 + mo + kx[s][1]];
                af[mt][3] = as[abase1 + mo + kx[s][1]];
            }
#pragma unroll
            for (int nt = 0; nt < 4; nt++) {
                int base = (wn * 4 + nt) * 256 + s * 64;
                bf[nt][0] = bs[base + rotB[nt]];
                bf[nt][1] = bs[base + 32 + rotB[nt]];
            }
#pragma unroll
            for (int mt = 0; mt < 4; mt++)
#pragma unroll
                for (int nt = 0; nt < 4; nt++)
                    mma_tf32(acc[mt][nt], af[mt], bf[nt]);
        }

        if (bnext) {
            uint32_t* bsn = Bsm + ((kt + 1) & 1) * 4096;
            const float* v = (const float*)bv;
#pragma unroll
            for (int j = 0; j < 8; j++) {
                bsn[bb1 + brot[j]]       = __float_as_uint(v[j]);
                bsn[bb1 + 128 + brot[j]] = __float_as_uint(v[j + 8]);
            }
        }
    }
    cp_wait0();

    // epilogue
    int gc = lane >> 2, tc = lane & 3;
#pragma unroll
    for (int mt = 0; mt < 4; mt++) {
        int m0 = by * 128 + wm * 64 + mt * 16 + gc;
#pragma unroll
        for (int nt = 0; nt < 4; nt++) {
            int n = bx * 128 + wn * 32 + nt * 8 + tc * 2;
            float b0v = do_bias ? bias[n] : 0.f;
            float b1v = do_bias ? bias[n + 1] : 0.f;
            float v0 = acc[mt][nt][0] + b0v;
            float v1 = acc[mt][nt][1] + b1v;
            float v2 = acc[mt][nt][2] + b0v;
            float v3 = acc[mt][nt][3] + b1v;
            float* c0 = C + (size_t)m0 * N + n;
            float* c1 = C + (size_t)(m0 + 8) * N + n;
            if (do_accum) {
                float2 o0 = *(const float2*)c0;
                float2 o1 = *(const float2*)c1;
                v0 += o0.x; v1 += o0.y; v2 += o1.x; v3 += o1.y;
            }
            if (do_relu) {
                v0 = fmaxf(v0, 0.f); v1 = fmaxf(v1, 0.f);
                v2 = fmaxf(v2, 0.f); v3 = fmaxf(v3, 0.f);
            }
            if (do_round) {
                v0 = rndtf(v0); v1 = rndtf(v1);
                v2 = rndtf(v2); v3 = rndtf(v3);
            }
            *(float2*)c0 = make_float2(v0, v1);
            *(float2*)c1 = make_float2(v2, v3);
        }
    }
}

// ---------------------------------------------------------------------------
// Fused layers 3+4
// ---------------------------------------------------------------------------
__global__ __launch_bounds__(256) void tail_kernel(
    const float* __restrict__ W3, const float* __restrict__ b3,
    const float* __restrict__ W4, const float* __restrict__ b4,
    float* __restrict__ out)
{
    __shared__ float sW3[128 * 64];
    __shared__ float sb3[64];
    __shared__ float sW4[64];
    int tid = threadIdx.x;
    for (int i = tid; i < 128 * 64; i += 256) sW3[i] = W3[i];
    if (tid < 64) { sb3[tid] = b3[tid]; sW4[tid] = W4[tid]; }
    __syncthreads();

    int s = blockIdx.x * 256 + tid;
    if (s >= BATCH) return;
    const float4* h2r = (const float4*)(g_h2 + (size_t)s * 128);

    float h3[64];
#pragma unroll
    for (int o = 0; o < 64; o++) h3[o] = sb3[o];

    for (int k4 = 0; k4 < 32; k4++) {
        float4 v = h2r[k4];
        float hv[4] = {v.x, v.y, v.z, v.w};
#pragma unroll
        for (int u = 0; u < 4; u++) {
            const float* wrow = &sW3[(k4 * 4 + u) * 64];
#pragma unroll
            for (int o = 0; o < 64; o++) h3[o] = fmaf(hv[u], wrow[o], h3[o]);
        }
    }
    float accv = b4[0];
#pragma unroll
    for (int o = 0; o < 64; o++) accv = fmaf(fmaxf(h3[o], 0.f), sW4[o], accv);
    out[s] = accv;
}

// ---------------------------------------------------------------------------
extern "C" void kernel_launch(void* const* d_in, const int* in_sizes, int n_in,
                              void* d_out, int out_size) {
    const float* x  = (const float*)d_in[0];
    const float* W1 = (const float*)d_in[1];
    const float* b1 = (const float*)d_in[2];
    const float* W2 = (const float*)d_in[3];
    const float* b2 = (const float*)d_in[4];
    const float* W3 = (const float*)d_in[5];
    const float* b3 = (const float*)d_in[6];
    const float* W4 = (const float*)d_in[7];
    const float* b4 = (const float*)d_in[8];
    float* out = (float*)d_out;

    float *feats, *h1, *h2, *w1r, *w2r;
    cudaGetSymbolAddress((void**)&feats, g_feats);
    cudaGetSymbolAddress((void**)&h1, g_h1);
    cudaGetSymbolAddress((void**)&h2, g_h2);
    cudaGetSymbolAddress((void**)&w1r, g_w1r);
    cudaGetSymbolAddress((void**)&w2r, g_w2r);

    static cudaStream_t s2;
    static cudaEvent_t ev_feat, ev_svd;
    static int inited = 0;
    if (!inited) {
        cudaFuncSetAttribute(gemm_tf32_pipe,
                             cudaFuncAttributeMaxDynamicSharedMemorySize, 81920);
        cudaFuncSetAttribute(svd_kernel,
                             cudaFuncAttributeMaxDynamicSharedMemorySize, 70144);
        cudaStreamCreateWithFlags(&s2, cudaStreamNonBlocking);
        cudaEventCreateWithFlags(&ev_feat, cudaEventDisableTiming);
        cudaEventCreateWithFlags(&ev_svd, cudaEventDisableTiming);
        inited = 1;
    }

    // weight pre-rounding
    round_copy<<<(FEAT * 256 + 255) / 256, 256>>>(W1, w1r, FEAT * 256);
    round_copy<<<(256 * 128 + 255) / 256, 256>>>(W2, w2r, 256 * 128);

    feat_kernel<<<BATCH / 8, 256>>>(x);

    // fork: svd (writes feats[1792:1808]) runs concurrently with gemm1-main
    cudaEventRecord(ev_feat, 0);
    cudaStreamWaitEvent(s2, ev_feat, 0);
    svd_kernel<<<BATCH / 128, 128, 70144, s2>>>();

    // layer-1 main: K tiles 0..55 (k < 1792, independent of svd), raw partials
    {
        dim3 grid(2, BATCH / 128);
        gemm_tf32_pipe<<<grid, 256, 81920>>>(BATCH, 256, FEAT, FEAT, 56,
                                             feats, w1r, w1r, h1, 0, 0, 0, 0);
    }

    // join: svd must finish before the K tail (k in [1792,1808))
    cudaEventRecord(ev_svd, s2);
    cudaStreamWaitEvent(0, ev_svd, 0);

    // layer-1 tail: 1 K-tile, accumulate + bias + relu + round
    {
        dim3 grid(2, BATCH / 128);
        gemm_tf32_pipe<<<grid, 256, 81920>>>(BATCH, 256, FEAT, 16, 1,
                                             feats + 1792, w1r + (size_t)1792 * 256,
                                             b1, h1, 1, 1, 1, 1);
    }

    // layer 2: [B,256] @ [256,128] + b2, relu
    {
        dim3 grid(1, BATCH / 128);
        gemm_tf32_pipe<<<grid, 256, 81920>>>(BATCH, 128, 256, 256, 8,
                                             h1, w2r, b2, h2, 1, 0, 0, 1);
    }
    tail_kernel<<<BATCH / 256, 256>>>(W3, b3, W4, b4, out);
}

// round 15
// speedup vs baseline: 1.1715x; 1.0600x over previous
#include <cuda_runtime.h>
#include <math.h>
#include <stdint.h>

#define BATCH 65536
#define FEAT  1808

// Scratch (static device globals; no allocation in kernel_launch)
__device__ float g_feats[(size_t)BATCH * FEAT + 16];  // +16: A-tail overread pad
__device__ float g_w1r[(size_t)FEAT * 256];           // tf32-rounded W1
__device__ float g_w2r[(size_t)256 * 128];            // tf32-rounded W2
__device__ float g_h1[(size_t)BATCH * 256];
__device__ float g_h2[(size_t)BATCH * 128];

// ---------------------------------------------------------------------------
// helpers
// ---------------------------------------------------------------------------
__device__ __forceinline__ uint32_t f2tf(float f) {
    uint32_t u;
    asm("cvt.rna.tf32.f32 %0, %1;" : "=r"(u) : "f"(f));
    return u;
}
__device__ __forceinline__ float rndtf(float f) {
    return __uint_as_float(f2tf(f));
}
__device__ __forceinline__ uint32_t smem_u32(const void* p) {
    uint32_t a;
    asm("{ .reg .u64 t; cvta.to.shared.u64 t, %1; cvt.u32.u64 %0, t; }"
        : "=r"(a) : "l"(p));
    return a;
}
__device__ __forceinline__ void cp_async16(uint32_t dst, const void* src) {
    asm volatile("cp.async.cg.shared.global [%0], [%1], 16;\n"
                 :: "r"(dst), "l"(src));
}
__device__ __forceinline__ void cp_commit() {
    asm volatile("cp.async.commit_group;\n" ::: "memory");
}
__device__ __forceinline__ void cp_wait1() {
    asm volatile("cp.async.wait_group 1;\n" ::: "memory");
}
__device__ __forceinline__ void cp_wait0() {
    asm volatile("cp.async.wait_group 0;\n" ::: "memory");
}
__device__ __forceinline__ void mma_tf32(float* d, const uint32_t* a, const uint32_t* b) {
    asm volatile(
        "mma.sync.aligned.m16n8k8.row.col.f32.tf32.tf32.f32 "
        "{%0,%1,%2,%3}, {%4,%5,%6,%7}, {%8,%9}, {%0,%1,%2,%3};"
        : "+f"(d[0]), "+f"(d[1]), "+f"(d[2]), "+f"(d[3])
        : "r"(a[0]), "r"(a[1]), "r"(a[2]), "r"(a[3]), "r"(b[0]), "r"(b[1]));
}

// ---------------------------------------------------------------------------
// Weight pre-rounding (tf32-rna) into device globals
// ---------------------------------------------------------------------------
__global__ void round_copy(const float* __restrict__ src, float* __restrict__ dst, int n) {
    int i = blockIdx.x * blockDim.x + threadIdx.x;
    if (i < n) dst[i] = rndtf(src[i]);
}

// ---------------------------------------------------------------------------
// Kernel 1: features, warp/sample — writes tf32-rounded values
// ---------------------------------------------------------------------------
__global__ __launch_bounds__(256) void feat_kernel(const float* __restrict__ x) {
    int gw = (blockIdx.x * blockDim.x + threadIdx.x) >> 5;
    int lane = threadIdx.x & 31;
    if (gw >= BATCH) return;
    const float* xr = x + (size_t)gw * 512;
    float* fr = g_feats + (size_t)gw * FEAT;

    float c[16];
#pragma unroll
    for (int k = 0; k < 16; k++) c[k] = xr[k * 32 + lane];
#pragma unroll
    for (int k = 0; k < 16; k++) fr[k * 32 + lane] = rndtf(c[k]);

#pragma unroll
    for (int i = 0; i < 32; i++) {
        float acc = 0.f;
#pragma unroll
        for (int k = 0; k < 16; k++)
            acc = fmaf(__shfl_sync(0xffffffffu, c[k], i), c[k], acc);
        fr[512 + i * 32 + lane] = rndtf(acc);
    }

    float outv[8];
#pragma unroll
    for (int r = 0; r < 8; r++) outv[r] = 0.f;
#pragma unroll
    for (int i = 0; i < 16; i++) {
#pragma unroll
        for (int j = i; j < 16; j++) {
            float v = c[i] * c[j];
            v += __shfl_xor_sync(0xffffffffu, v, 16);
            v += __shfl_xor_sync(0xffffffffu, v, 8);
            v += __shfl_xor_sync(0xffffffffu, v, 4);
            v += __shfl_xor_sync(0xffffffffu, v, 2);
            v += __shfl_xor_sync(0xffffffffu, v, 1);
            int p1 = i * 16 + j;
            if (lane == (p1 & 31)) outv[p1 >> 5] = v;
            if (i != j) {
                int p2 = j * 16 + i;
                if (lane == (p2 & 31)) outv[p2 >> 5] = v;
            }
        }
    }
#pragma unroll
    for (int r = 0; r < 8; r++) fr[1536 + r * 32 + lane] = rndtf(outv[r]);
}

// ---------------------------------------------------------------------------
// Kernel 2: SVD via cyclic Jacobi on 16x16 Gram in shared memory.
// One sample/thread, 3 sweeps (4->5 sweep delta was 1.3e-6: already in the
// tf32 noise floor; 3-sweep eigenvalue error ~1e-6 rel, budget is 1e-3),
// 128-thread blocks, 3 blocks/SM.
// ---------------------------------------------------------------------------
__device__ __forceinline__ constexpr int SIDX(int i, int j) {
    return i * 16 - i * (i - 1) / 2 + (j - i);
}
__device__ __forceinline__ int ROFF(int i) {
    return i * 16 - i * (i - 1) / 2 - i;
}

__global__ __launch_bounds__(128, 3) void svd_kernel() {
    extern __shared__ float sa[];
    int t = threadIdx.x;
    size_t s = (size_t)blockIdx.x * 128 + t;
    float* fr = g_feats + s * FEAT;
    float* m = sa + t * 137;

#pragma unroll
    for (int i = 0; i < 16; i++)
#pragma unroll
        for (int j = i; j < 16; j++)
            m[SIDX(i, j)] = fr[1536 + i * 16 + j];

#pragma unroll 1
    for (int sw = 0; sw < 3; sw++) {
#pragma unroll 1
        for (int p = 0; p < 15; p++) {
            int roffp = ROFF(p);
#pragma unroll 1
            for (int q = p + 1; q < 16; q++) {
                int roffq = ROFF(q);
                float apq = m[roffp + q];
                float app = m[roffp + p];
                float aqq = m[roffq + q];
                float theta = __fdividef(0.5f * (aqq - app), apq);
                float tt = copysignf(1.0f, theta) /
                           (fabsf(theta) + sqrtf(fmaf(theta, theta, 1.0f)));
                tt = (apq == 0.0f) ? 0.0f : tt;
                float cth = rsqrtf(fmaf(tt, tt, 1.0f));
                float sth = tt * cth;
                m[roffp + p] = app - tt * apq;
                m[roffq + q] = aqq + tt * apq;
                m[roffp + q] = 0.f;
#pragma unroll
                for (int i = 0; i < 16; i++) {
                    int ip = (i < p) ? (ROFF(i) + p) : (roffp + i);
                    int iq = (i < q) ? (ROFF(i) + q) : (roffq + i);
                    float aip = m[ip], aiq = m[iq];
                    float n1 = cth * aip - sth * aiq;
                    float n2 = sth * aip + cth * aiq;
                    if (i != p && i != q) { m[ip] = n1; m[iq] = n2; }
                }
            }
        }
    }

    float sv[16];
#pragma unroll
    for (int i = 0; i < 16; i++) sv[i] = sqrtf(fmaxf(m[ROFF(i) + i], 0.f));

#pragma unroll
    for (int i = 0; i < 15; i++)
#pragma unroll
        for (int j = 0; j < 15 - i; j++) {
            float hi = fmaxf(sv[j], sv[j + 1]);
            float lo = fminf(sv[j], sv[j + 1]);
            sv[j] = hi;
            sv[j + 1] = lo;
        }
    float4* o = (float4*)(fr + 1792);
#pragma unroll
    for (int i = 0; i < 4; i++)
        o[i] = make_float4(rndtf(sv[i * 4]), rndtf(sv[i * 4 + 1]),
                           rndtf(sv[i * 4 + 2]), rndtf(sv[i * 4 + 3]));
}

// ---------------------------------------------------------------------------
// Pipelined TF32 GEMM: C = epilogue(A @ B [+ C] [+ bias]). Inputs pre-rounded
// to tf32. Block 128x128, warp 64x32, BK=32, cp.async 3-stage A pipeline.
// Ka = A row stride; Kb = valid B rows (rows >= Kb read as zero).
// do_accum: C += partial (for K-split). do_bias/do_relu/do_round: epilogue.
// dynamic smem: A 3*16KB + B 2*16KB = 80KB
// ---------------------------------------------------------------------------
__global__ __launch_bounds__(256, 2) void gemm_tf32_pipe(
    int M, int N, int Ka, int Kb, int NTt,
    const float* __restrict__ A,
    const float* __restrict__ Bw,
    const float* __restrict__ bias,
    float* __restrict__ C,
    int do_relu, int do_round, int do_accum, int do_bias)
{
    extern __shared__ uint32_t sm[];
    uint32_t* Asm = sm;               // 3 stages x 4096 words
    uint32_t* Bsm = sm + 3 * 4096;    // 2 bufs x 4096 words
    uint32_t sbase = smem_u32(sm);

    int tid = threadIdx.x;
    int bx = blockIdx.x, by = blockIdx.y;
    int warp = tid >> 5, lane = tid & 31;
    int wm = warp >> 2, wn = warp & 3;

    // ---- A cp.async addressing ----
    int am = tid >> 1;                    // 0..127
    int ak0 = (tid & 1) * 16;             // 0 or 16
    int axr = 4 * (am & 7);
    uint32_t adst[4];
#pragma unroll
    for (int j = 0; j < 4; j++)
        adst[j] = (uint32_t)(am * 32 + ((ak0 + 4 * j) ^ axr)) * 4;
    const float* aptr = A + (size_t)(by * 128 + am) * Ka + ak0;

    // ---- B loader addressing ----
    int rowB0 = tid >> 4;                 // 0..15
    int nt0 = tid & 15;
    int colB = nt0 * 8;
    int kk = rowB0 & 7, tB = kk & 3, rB = kk >> 2, ks0 = rowB0 >> 3;
    int bb1 = nt0 * 256 + ks0 * 64 + rB * 32;
    int brot[8];
#pragma unroll
    for (int j = 0; j < 8; j++) brot[j] = (4 * j + tB + 2 * nt0) & 31;
    const float* bptr = Bw + (size_t)rowB0 * N + bx * 128 + colB;

    // ---- fragment read addressing ----
    int q = lane >> 2, t4 = lane & 3;
    int abase0 = (wm * 64 + q) * 32;
    int abase1 = abase0 + 8 * 32;
    int kx[4][2];
#pragma unroll
    for (int s = 0; s < 4; s++)
#pragma unroll
        for (int h = 0; h < 2; h++)
            kx[s][h] = t4 + 4 * (((2 * s + h) ^ q) & 7);
    int rotB[4];
#pragma unroll
    for (int nt = 0; nt < 4; nt++)
        rotB[nt] = (lane + 2 * (wn * 4 + nt)) & 31;

    float acc[4][4][4];
#pragma unroll
    for (int mt = 0; mt < 4; mt++)
#pragma unroll
        for (int nt = 0; nt < 4; nt++)
#pragma unroll
            for (int r = 0; r < 4; r++) acc[mt][nt][r] = 0.f;

    // ---- prologue ----
#pragma unroll
    for (int st = 0; st < 2; st++) {
        if (st < NTt) {
#pragma unroll
            for (int j = 0; j < 4; j++)
                cp_async16(sbase + (uint32_t)st * 16384 + adst[j],
                           aptr + (size_t)st * 32 + 4 * j);
        }
        cp_commit();
    }
    float4 bv[4];
    {
        int k2 = rowB0 + 16;
        bv[0] = *(const float4*)(bptr);
        bv[1] = *(const float4*)(bptr + 4);
        bv[2] = (k2 < Kb) ? *(const float4*)(bptr + (size_t)16 * N)
                          : make_float4(0.f, 0.f, 0.f, 0.f);
        bv[3] = (k2 < Kb) ? *(const float4*)(bptr + (size_t)16 * N + 4)
                          : make_float4(0.f, 0.f, 0.f, 0.f);
        uint32_t* bs = Bsm;
        const float* v = (const float*)bv;
#pragma unroll
        for (int j = 0; j < 8; j++) {
            bs[bb1 + brot[j]]       = __float_as_uint(v[j]);
            bs[bb1 + 128 + brot[j]] = __float_as_uint(v[j + 8]);
        }
    }

#pragma unroll 1
    for (int kt = 0; kt < NTt; kt++) {
        cp_wait1();
        __syncthreads();

        if (kt + 2 < NTt) {
#pragma unroll
            for (int j = 0; j < 4; j++)
                cp_async16(sbase + (uint32_t)((kt + 2) % 3) * 16384 + adst[j],
                           aptr + (size_t)(kt + 2) * 32 + 4 * j);
        }
        cp_commit();

        bool bnext = (kt + 1) < NTt;
        if (bnext) {
            int kb = (kt + 1) * 32;
            int k1 = kb + rowB0, k2 = k1 + 16;
            const float* bp = bptr + (size_t)kb * N;
            bv[0] = (k1 < Kb) ? *(const float4*)(bp)
                              : make_float4(0.f, 0.f, 0.f, 0.f);
            bv[1] = (k1 < Kb) ? *(const float4*)(bp + 4)
                              : make_float4(0.f, 0.f, 0.f, 0.f);
            bv[2] = (k2 < Kb) ? *(const float4*)(bp + (size_t)16 * N)
                              : make_float4(0.f, 0.f, 0.f, 0.f);
            bv[3] = (k2 < Kb) ? *(const float4*)(bp + (size_t)16 * N + 4)
                              : make_float4(0.f, 0.f, 0.f, 0.f);
        }

        const uint32_t* as = Asm + (kt % 3) * 4096;
        const uint32_t* bs = Bsm + (kt & 1) * 4096;
#pragma unroll
        for (int s = 0; s < 4; s++) {
            uint32_t af[4][4];
            uint32_t bf[4][2];
#pragma unroll
            for (int mt = 0; mt < 4; mt++) {
                int mo = mt * 512;
                af[mt][0] = as[abase0 + mo + kx[s][0]];
                af[mt][1] = as[abase1 + mo + kx[s][0]];
                af[mt][2] = as[abase0 + mo + kx[s][1]];
                af[mt][3] = as[abase1 + mo + kx[s][1]];
            }
#pragma unroll
            for (int nt = 0; nt < 4; nt++) {
                int base = (wn * 4 + nt) * 256 + s * 64;
                bf[nt][0] = bs[base + rotB[nt]];
                bf[nt][1] = bs[base + 32 + rotB[nt]];
            }
#pragma unroll
            for (int mt = 0; mt < 4; mt++)
#pragma unroll
                for (int nt = 0; nt < 4; nt++)
                    mma_tf32(acc[mt][nt], af[mt], bf[nt]);
        }

        if (bnext) {
            uint32_t* bsn = Bsm + ((kt + 1) & 1) * 4096;
            const float* v = (const float*)bv;
#pragma unroll
            for (int j = 0; j < 8; j++) {
                bsn[bb1 + brot[j]]       = __float_as_uint(v[j]);
                bsn[bb1 + 128 + brot[j]] = __float_as_uint(v[j + 8]);
            }
        }
    }
    cp_wait0();

    // epilogue
    int gc = lane >> 2, tc = lane & 3;
#pragma unroll
    for (int mt = 0; mt < 4; mt++) {
        int m0 = by * 128 + wm * 64 + mt * 16 + gc;
#pragma unroll
        for (int nt = 0; nt < 4; nt++) {
            int n = bx * 128 + wn * 32 + nt * 8 + tc * 2;
            float b0v = do_bias ? bias[n] : 0.f;
            float b1v = do_bias ? bias[n + 1] : 0.f;
            float v0 = acc[mt][nt][0] + b0v;
            float v1 = acc[mt][nt][1] + b1v;
            float v2 = acc[mt][nt][2] + b0v;
            float v3 = acc[mt][nt][3] + b1v;
            float* c0 = C + (size_t)m0 * N + n;
            float* c1 = C + (size_t)(m0 + 8) * N + n;
            if (do_accum) {
                float2 o0 = *(const float2*)c0;
                float2 o1 = *(const float2*)c1;
                v0 += o0.x; v1 += o0.y; v2 += o1.x; v3 += o1.y;
            }
            if (do_relu) {
                v0 = fmaxf(v0, 0.f); v1 = fmaxf(v1, 0.f);
                v2 = fmaxf(v2, 0.f); v3 = fmaxf(v3, 0.f);
            }
            if (do_round) {
                v0 = rndtf(v0); v1 = rndtf(v1);
                v2 = rndtf(v2); v3 = rndtf(v3);
            }
            *(float2*)c0 = make_float2(v0, v1);
            *(float2*)c1 = make_float2(v2, v3);
        }
    }
}

// ---------------------------------------------------------------------------
// Fused layers 3+4
// ---------------------------------------------------------------------------
__global__ __launch_bounds__(256) void tail_kernel(
    const float* __restrict__ W3, const float* __restrict__ b3,
    const float* __restrict__ W4, const float* __restrict__ b4,
    float* __restrict__ out)
{
    __shared__ float sW3[128 * 64];
    __shared__ float sb3[64];
    __shared__ float sW4[64];
    int tid = threadIdx.x;
    for (int i = tid; i < 128 * 64; i += 256) sW3[i] = W3[i];
    if (tid < 64) { sb3[tid] = b3[tid]; sW4[tid] = W4[tid]; }
    __syncthreads();

    int s = blockIdx.x * 256 + tid;
    if (s >= BATCH) return;
    const float4* h2r = (const float4*)(g_h2 + (size_t)s * 128);

    float h3[64];
#pragma unroll
    for (int o = 0; o < 64; o++) h3[o] = sb3[o];

    for (int k4 = 0; k4 < 32; k4++) {
        float4 v = h2r[k4];
        float hv[4] = {v.x, v.y, v.z, v.w};
#pragma unroll
        for (int u = 0; u < 4; u++) {
            const float* wrow = &sW3[(k4 * 4 + u) * 64];
#pragma unroll
            for (int o = 0; o < 64; o++) h3[o] = fmaf(hv[u], wrow[o], h3[o]);
        }
    }
    float accv = b4[0];
#pragma unroll
    for (int o = 0; o < 64; o++) accv = fmaf(fmaxf(h3[o], 0.f), sW4[o], accv);
    out[s] = accv;
}

// ---------------------------------------------------------------------------
extern "C" void kernel_launch(void* const* d_in, const int* in_sizes, int n_in,
                              void* d_out, int out_size) {
    const float* x  = (const float*)d_in[0];
    const float* W1 = (const float*)d_in[1];
    const float* b1 = (const float*)d_in[2];
    const float* W2 = (const float*)d_in[3];
    const float* b2 = (const float*)d_in[4];
    const float* W3 = (const float*)d_in[5];
    const float* b3 = (const float*)d_in[6];
    const float* W4 = (const float*)d_in[7];
    const float* b4 = (const float*)d_in[8];
    float* out = (float*)d_out;

    float *feats, *h1, *h2, *w1r, *w2r;
    cudaGetSymbolAddress((void**)&feats, g_feats);
    cudaGetSymbolAddress((void**)&h1, g_h1);
    cudaGetSymbolAddress((void**)&h2, g_h2);
    cudaGetSymbolAddress((void**)&w1r, g_w1r);
    cudaGetSymbolAddress((void**)&w2r, g_w2r);

    static cudaStream_t s2;
    static cudaEvent_t ev_feat, ev_svd;
    static int inited = 0;
    if (!inited) {
        cudaFuncSetAttribute(gemm_tf32_pipe,
                             cudaFuncAttributeMaxDynamicSharedMemorySize, 81920);
        cudaFuncSetAttribute(svd_kernel,
                             cudaFuncAttributeMaxDynamicSharedMemorySize, 70144);
        cudaStreamCreateWithFlags(&s2, cudaStreamNonBlocking);
        cudaEventCreateWithFlags(&ev_feat, cudaEventDisableTiming);
        cudaEventCreateWithFlags(&ev_svd, cudaEventDisableTiming);
        inited = 1;
    }

    // weight pre-rounding
    round_copy<<<(FEAT * 256 + 255) / 256, 256>>>(W1, w1r, FEAT * 256);
    round_copy<<<(256 * 128 + 255) / 256, 256>>>(W2, w2r, 256 * 128);

    feat_kernel<<<BATCH / 8, 256>>>(x);

    // fork: svd (writes feats[1792:1808]) runs concurrently with gemm1-main
    cudaEventRecord(ev_feat, 0);
    cudaStreamWaitEvent(s2, ev_feat, 0);
    svd_kernel<<<BATCH / 128, 128, 70144, s2>>>();

    // layer-1 main: K tiles 0..55 (k < 1792, independent of svd), raw partials
    {
        dim3 grid(2, BATCH / 128);
        gemm_tf32_pipe<<<grid, 256, 81920>>>(BATCH, 256, FEAT, FEAT, 56,
                                             feats, w1r, w1r, h1, 0, 0, 0, 0);
    }

    // join: svd must finish before the K tail (k in [1792,1808))
    cudaEventRecord(ev_svd, s2);
    cudaStreamWaitEvent(0, ev_svd, 0);

    // layer-1 tail: 1 K-tile, accumulate + bias + relu + round
    {
        dim3 grid(2, BATCH / 128);
        gemm_tf32_pipe<<<grid, 256, 81920>>>(BATCH, 256, FEAT, 16, 1,
                                             feats + 1792, w1r + (size_t)1792 * 256,
                                             b1, h1, 1, 1, 1, 1);
    }

    // layer 2: [B,256] @ [256,128] + b2, relu
    {
        dim3 grid(1, BATCH / 128);
        gemm_tf32_pipe<<<grid, 256, 81920>>>(BATCH, 128, 256, 256, 8,
                                             h1, w2r, b2, h2, 1, 0, 0, 1);
    }
    tail_kernel<<<BATCH / 256, 256>>>(W3, b3, W4, b4, out);
}

// round 16
// speedup vs baseline: 1.2049x; 1.0285x over previous
#include <cuda_runtime.h>
#include <math.h>
#include <stdint.h>

#define BATCH 65536
#define FEAT  1808

// Scratch (static device globals; no allocation in kernel_launch)
__device__ float g_feats[(size_t)BATCH * FEAT + 16];  // +16: A-tail overread pad
__device__ float g_w1r[(size_t)FEAT * 256];           // tf32-rounded W1
__device__ float g_w2r[(size_t)256 * 128];            // tf32-rounded W2
__device__ float g_h1[(size_t)BATCH * 256];
__device__ float g_h2[(size_t)BATCH * 128];

// ---------------------------------------------------------------------------
// helpers
// ---------------------------------------------------------------------------
__device__ __forceinline__ uint32_t f2tf(float f) {
    uint32_t u;
    asm("cvt.rna.tf32.f32 %0, %1;" : "=r"(u) : "f"(f));
    return u;
}
__device__ __forceinline__ float rndtf(float f) {
    return __uint_as_float(f2tf(f));
}
__device__ __forceinline__ uint32_t smem_u32(const void* p) {
    uint32_t a;
    asm("{ .reg .u64 t; cvta.to.shared.u64 t, %1; cvt.u32.u64 %0, t; }"
        : "=r"(a) : "l"(p));
    return a;
}
__device__ __forceinline__ void cp_async16(uint32_t dst, const void* src) {
    asm volatile("cp.async.cg.shared.global [%0], [%1], 16;\n"
                 :: "r"(dst), "l"(src));
}
// zero-fill variant: src-size 0 -> 16 bytes of zeros (used for K-tail rows)
__device__ __forceinline__ void cp_async16z(uint32_t dst, const void* src, uint32_t sz) {
    asm volatile("cp.async.cg.shared.global [%0], [%1], 16, %2;\n"
                 :: "r"(dst), "l"(src), "r"(sz));
}
__device__ __forceinline__ void cp_commit() {
    asm volatile("cp.async.commit_group;\n" ::: "memory");
}
__device__ __forceinline__ void cp_wait1() {
    asm volatile("cp.async.wait_group 1;\n" ::: "memory");
}
__device__ __forceinline__ void cp_wait0() {
    asm volatile("cp.async.wait_group 0;\n" ::: "memory");
}
__device__ __forceinline__ void mma_tf32(float* d, const uint32_t* a, const uint32_t* b) {
    asm volatile(
        "mma.sync.aligned.m16n8k8.row.col.f32.tf32.tf32.f32 "
        "{%0,%1,%2,%3}, {%4,%5,%6,%7}, {%8,%9}, {%0,%1,%2,%3};"
        : "+f"(d[0]), "+f"(d[1]), "+f"(d[2]), "+f"(d[3])
        : "r"(a[0]), "r"(a[1]), "r"(a[2]), "r"(a[3]), "r"(b[0]), "r"(b[1]));
}

// ---------------------------------------------------------------------------
// Weight pre-rounding (tf32-rna) into device globals
// ---------------------------------------------------------------------------
__global__ void round_copy(const float* __restrict__ src, float* __restrict__ dst, int n) {
    int i = blockIdx.x * blockDim.x + threadIdx.x;
    if (i < n) dst[i] = rndtf(src[i]);
}

// ---------------------------------------------------------------------------
// Kernel 1: features, warp/sample — writes tf32-rounded values
// ---------------------------------------------------------------------------
__global__ __launch_bounds__(256) void feat_kernel(const float* __restrict__ x) {
    int gw = (blockIdx.x * blockDim.x + threadIdx.x) >> 5;
    int lane = threadIdx.x & 31;
    if (gw >= BATCH) return;
    const float* xr = x + (size_t)gw * 512;
    float* fr = g_feats + (size_t)gw * FEAT;

    float c[16];
#pragma unroll
    for (int k = 0; k < 16; k++) c[k] = xr[k * 32 + lane];
#pragma unroll
    for (int k = 0; k < 16; k++) fr[k * 32 + lane] = rndtf(c[k]);

#pragma unroll
    for (int i = 0; i < 32; i++) {
        float acc = 0.f;
#pragma unroll
        for (int k = 0; k < 16; k++)
            acc = fmaf(__shfl_sync(0xffffffffu, c[k], i), c[k], acc);
        fr[512 + i * 32 + lane] = rndtf(acc);
    }

    float outv[8];
#pragma unroll
    for (int r = 0; r < 8; r++) outv[r] = 0.f;
#pragma unroll
    for (int i = 0; i < 16; i++) {
#pragma unroll
        for (int j = i; j < 16; j++) {
            float v = c[i] * c[j];
            v += __shfl_xor_sync(0xffffffffu, v, 16);
            v += __shfl_xor_sync(0xffffffffu, v, 8);
            v += __shfl_xor_sync(0xffffffffu, v, 4);
            v += __shfl_xor_sync(0xffffffffu, v, 2);
            v += __shfl_xor_sync(0xffffffffu, v, 1);
            int p1 = i * 16 + j;
            if (lane == (p1 & 31)) outv[p1 >> 5] = v;
            if (i != j) {
                int p2 = j * 16 + i;
                if (lane == (p2 & 31)) outv[p2 >> 5] = v;
            }
        }
    }
#pragma unroll
    for (int r = 0; r < 8; r++) fr[1536 + r * 32 + lane] = rndtf(outv[r]);
}

// ---------------------------------------------------------------------------
// Kernel 2: SVD via cyclic Jacobi on 16x16 Gram in shared memory.
// One sample/thread, 3 sweeps, 128-thread blocks, 3 blocks/SM.
// ---------------------------------------------------------------------------
__device__ __forceinline__ constexpr int SIDX(int i, int j) {
    return i * 16 - i * (i - 1) / 2 + (j - i);
}
__device__ __forceinline__ int ROFF(int i) {
    return i * 16 - i * (i - 1) / 2 - i;
}

__global__ __launch_bounds__(128, 3) void svd_kernel() {
    extern __shared__ float sa[];
    int t = threadIdx.x;
    size_t s = (size_t)blockIdx.x * 128 + t;
    float* fr = g_feats + s * FEAT;
    float* m = sa + t * 137;

#pragma unroll
    for (int i = 0; i < 16; i++)
#pragma unroll
        for (int j = i; j < 16; j++)
            m[SIDX(i, j)] = fr[1536 + i * 16 + j];

#pragma unroll 1
    for (int sw = 0; sw < 3; sw++) {
#pragma unroll 1
        for (int p = 0; p < 15; p++) {
            int roffp = ROFF(p);
#pragma unroll 1
            for (int q = p + 1; q < 16; q++) {
                int roffq = ROFF(q);
                float apq = m[roffp + q];
                float app = m[roffp + p];
                float aqq = m[roffq + q];
                float theta = __fdividef(0.5f * (aqq - app), apq);
                float tt = copysignf(1.0f, theta) /
                           (fabsf(theta) + sqrtf(fmaf(theta, theta, 1.0f)));
                tt = (apq == 0.0f) ? 0.0f : tt;
                float cth = rsqrtf(fmaf(tt, tt, 1.0f));
                float sth = tt * cth;
                m[roffp + p] = app - tt * apq;
                m[roffq + q] = aqq + tt * apq;
                m[roffp + q] = 0.f;
#pragma unroll
                for (int i = 0; i < 16; i++) {
                    int ip = (i < p) ? (ROFF(i) + p) : (roffp + i);
                    int iq = (i < q) ? (ROFF(i) + q) : (roffq + i);
                    float aip = m[ip], aiq = m[iq];
                    float n1 = cth * aip - sth * aiq;
                    float n2 = sth * aip + cth * aiq;
                    if (i != p && i != q) { m[ip] = n1; m[iq] = n2; }
                }
            }
        }
    }

    float sv[16];
#pragma unroll
    for (int i = 0; i < 16; i++) sv[i] = sqrtf(fmaxf(m[ROFF(i) + i], 0.f));

#pragma unroll
    for (int i = 0; i < 15; i++)
#pragma unroll
        for (int j = 0; j < 15 - i; j++) {
            float hi = fmaxf(sv[j], sv[j + 1]);
            float lo = fminf(sv[j], sv[j + 1]);
            sv[j] = hi;
            sv[j + 1] = lo;
        }
    float4* o = (float4*)(fr + 1792);
#pragma unroll
    for (int i = 0; i < 4; i++)
        o[i] = make_float4(rndtf(sv[i * 4]), rndtf(sv[i * 4 + 1]),
                           rndtf(sv[i * 4 + 2]), rndtf(sv[i * 4 + 3]));
}

// ---------------------------------------------------------------------------
// Pipelined TF32 GEMM: C = epilogue(A @ B [+ C] [+ bias]). Inputs pre-rounded.
// Block 128x128, warp 64x32, BK=32. A AND B both via cp.async into a unified
// 3-stage ring (stage = A 16KB + B 16KB = 32KB; 96KB total, 2 CTAs/SM).
// A: XOR-swizzled row-major, word(m,k) = m*32 + (k ^ (4*(m&7))).
// B: row-major [k][128], chunk-swizzled: chunk pos = c ^ ((k&3)<<1 | (k>>2)&1)
//    -> conflict-free b-fragment LDS (bank = qn + 4*((2nt+q2)^(2t4+r))).
// K-tail rows (>= Kb) zero-filled via cp.async src-size 0.
// ---------------------------------------------------------------------------
__global__ __launch_bounds__(256, 2) void gemm_tf32_pipe(
    int M, int N, int Ka, int Kb, int NTt,
    const float* __restrict__ A,
    const float* __restrict__ Bw,
    const float* __restrict__ bias,
    float* __restrict__ C,
    int do_relu, int do_round, int do_accum, int do_bias)
{
    extern __shared__ uint32_t sm[];     // 3 stages x 8192 words (32KB)
    uint32_t sbase = smem_u32(sm);

    int tid = threadIdx.x;
    int bx = blockIdx.x, by = blockIdx.y;
    int warp = tid >> 5, lane = tid & 31;
    int wm = warp >> 2, wn = warp & 3;

    // ---- A cp.async addressing (byte offsets within stage) ----
    int am = tid >> 1;                    // 0..127
    int ak0 = (tid & 1) * 16;             // 0 or 16
    int axr = 4 * (am & 7);
    uint32_t adst[4];
#pragma unroll
    for (int j = 0; j < 4; j++)
        adst[j] = (uint32_t)(am * 32 + ((ak0 + 4 * j) ^ axr)) * 4;
    const float* aptr = A + (size_t)(by * 128 + am) * Ka + ak0;

    // ---- B cp.async addressing: 4 chunks/thread; chunk = tid + i*256 ----
    int brow[4], bc4[4];
    uint32_t bdst[4];
#pragma unroll
    for (int i = 0; i < 4; i++) {
        int chunk = tid + i * 256;
        int br = chunk >> 5;              // k row 0..31
        int bc = chunk & 31;              // chunk col 0..31
        int swz = ((br & 3) << 1) | ((br >> 2) & 1);
        brow[i] = br;
        bc4[i] = bc * 4;
        bdst[i] = (uint32_t)(16384 + br * 512 + (bc ^ swz) * 16);
    }
    const float* Bbase = Bw + bx * 128;

    // ---- fragment read addressing ----
    int q = lane >> 2, t4 = lane & 3;     // A: q = m-offset; B: q = n-offset, t4 = k-offset
    int abase0 = (wm * 64 + q) * 32;
    int abase1 = abase0 + 8 * 32;
    int kx[4][2];
#pragma unroll
    for (int s = 0; s < 4; s++)
#pragma unroll
        for (int h = 0; h < 2; h++)
            kx[s][h] = t4 + 4 * (((2 * s + h) ^ q) & 7);
    // B fragment word offsets (within stage, word units), s folded as +s*1024
    int q2 = q >> 2, qn = q & 3;
    int bfw[4][2];
#pragma unroll
    for (int nt = 0; nt < 4; nt++) {
        int pbase = wn * 8 + nt * 2 + q2;
#pragma unroll
        for (int r = 0; r < 2; r++) {
            int xr = 2 * t4 + r;
            bfw[nt][r] = 4096 + (r * 4 + t4) * 128 + ((pbase ^ xr) << 2) + qn;
        }
    }

    float acc[4][4][4];
#pragma unroll
    for (int mt = 0; mt < 4; mt++)
#pragma unroll
        for (int nt = 0; nt < 4; nt++)
#pragma unroll
            for (int r = 0; r < 4; r++) acc[mt][nt][r] = 0.f;

    // ---- stage issue: A (always valid) + B (zero-fill rows >= Kb) ----
    auto issue_stage = [&](int st) {
        uint32_t sb = sbase + (uint32_t)(st % 3) * 32768;
        const float* ap = aptr + (size_t)st * 32;
#pragma unroll
        for (int j = 0; j < 4; j++)
            cp_async16(sb + adst[j], ap + 4 * j);
        int kb = st * 32;
#pragma unroll
        for (int i = 0; i < 4; i++) {
            int k = kb + brow[i];
            uint32_t sz = (k < Kb) ? 16u : 0u;
            const float* src = (k < Kb) ? (Bbase + (size_t)k * N + bc4[i]) : Bbase;
            cp_async16z(sb + bdst[i], src, sz);
        }
        cp_commit();
    };

    // ---- prologue: stages 0,1 ----
#pragma unroll
    for (int st = 0; st < 2; st++) {
        if (st < NTt) issue_stage(st);
        else cp_commit();
    }

#pragma unroll 1
    for (int kt = 0; kt < NTt; kt++) {
        cp_wait1();          // stage kt resident (kt+1 may pend)
        __syncthreads();     // all warps done reading stage (kt-1)%3

        if (kt + 2 < NTt) issue_stage(kt + 2);
        else cp_commit();

        const uint32_t* as = sm + (kt % 3) * 8192;
#pragma unroll
        for (int s = 0; s < 4; s++) {
            uint32_t af[4][4];
            uint32_t bf[4][2];
#pragma unroll
            for (int mt = 0; mt < 4; mt++) {
                int mo = mt * 512;
                af[mt][0] = as[abase0 + mo + kx[s][0]];
                af[mt][1] = as[abase1 + mo + kx[s][0]];
                af[mt][2] = as[abase0 + mo + kx[s][1]];
                af[mt][3] = as[abase1 + mo + kx[s][1]];
            }
#pragma unroll
            for (int nt = 0; nt < 4; nt++) {
                bf[nt][0] = as[bfw[nt][0] + s * 1024];
                bf[nt][1] = as[bfw[nt][1] + s * 1024];
            }
#pragma unroll
            for (int mt = 0; mt < 4; mt++)
#pragma unroll
                for (int nt = 0; nt < 4; nt++)
                    mma_tf32(acc[mt][nt], af[mt], bf[nt]);
        }
    }
    cp_wait0();

    // epilogue
    int gc = lane >> 2, tc = lane & 3;
#pragma unroll
    for (int mt = 0; mt < 4; mt++) {
        int m0 = by * 128 + wm * 64 + mt * 16 + gc;
#pragma unroll
        for (int nt = 0; nt < 4; nt++) {
            int n = bx * 128 + wn * 32 + nt * 8 + tc * 2;
            float b0v = do_bias ? bias[n] : 0.f;
            float b1v = do_bias ? bias[n + 1] : 0.f;
            float v0 = acc[mt][nt][0] + b0v;
            float v1 = acc[mt][nt][1] + b1v;
            float v2 = acc[mt][nt][2] + b0v;
            float v3 = acc[mt][nt][3] + b1v;
            float* c0 = C + (size_t)m0 * N + n;
            float* c1 = C + (size_t)(m0 + 8) * N + n;
            if (do_accum) {
                float2 o0 = *(const float2*)c0;
                float2 o1 = *(const float2*)c1;
                v0 += o0.x; v1 += o0.y; v2 += o1.x; v3 += o1.y;
            }
            if (do_relu) {
                v0 = fmaxf(v0, 0.f); v1 = fmaxf(v1, 0.f);
                v2 = fmaxf(v2, 0.f); v3 = fmaxf(v3, 0.f);
            }
            if (do_round) {
                v0 = rndtf(v0); v1 = rndtf(v1);
                v2 = rndtf(v2); v3 = rndtf(v3);
            }
            *(float2*)c0 = make_float2(v0, v1);
            *(float2*)c1 = make_float2(v2, v3);
        }
    }
}

// ---------------------------------------------------------------------------
// Fused layers 3+4
// ---------------------------------------------------------------------------
__global__ __launch_bounds__(256) void tail_kernel(
    const float* __restrict__ W3, const float* __restrict__ b3,
    const float* __restrict__ W4, const float* __restrict__ b4,
    float* __restrict__ out)
{
    __shared__ float sW3[128 * 64];
    __shared__ float sb3[64];
    __shared__ float sW4[64];
    int tid = threadIdx.x;
    for (int i = tid; i < 128 * 64; i += 256) sW3[i] = W3[i];
    if (tid < 64) { sb3[tid] = b3[tid]; sW4[tid] = W4[tid]; }
    __syncthreads();

    int s = blockIdx.x * 256 + tid;
    if (s >= BATCH) return;
    const float4* h2r = (const float4*)(g_h2 + (size_t)s * 128);

    float h3[64];
#pragma unroll
    for (int o = 0; o < 64; o++) h3[o] = sb3[o];

    for (int k4 = 0; k4 < 32; k4++) {
        float4 v = h2r[k4];
        float hv[4] = {v.x, v.y, v.z, v.w};
#pragma unroll
        for (int u = 0; u < 4; u++) {
            const float* wrow = &sW3[(k4 * 4 + u) * 64];
#pragma unroll
            for (int o = 0; o < 64; o++) h3[o] = fmaf(hv[u], wrow[o], h3[o]);
        }
    }
    float accv = b4[0];
#pragma unroll
    for (int o = 0; o < 64; o++) accv = fmaf(fmaxf(h3[o], 0.f), sW4[o], accv);
    out[s] = accv;
}

// ---------------------------------------------------------------------------
extern "C" void kernel_launch(void* const* d_in, const int* in_sizes, int n_in,
                              void* d_out, int out_size) {
    const float* x  = (const float*)d_in[0];
    const float* W1 = (const float*)d_in[1];
    const float* b1 = (const float*)d_in[2];
    const float* W2 = (const float*)d_in[3];
    const float* b2 = (const float*)d_in[4];
    const float* W3 = (const float*)d_in[5];
    const float* b3 = (const float*)d_in[6];
    const float* W4 = (const float*)d_in[7];
    const float* b4 = (const float*)d_in[8];
    float* out = (float*)d_out;

    float *feats, *h1, *h2, *w1r, *w2r;
    cudaGetSymbolAddress((void**)&feats, g_feats);
    cudaGetSymbolAddress((void**)&h1, g_h1);
    cudaGetSymbolAddress((void**)&h2, g_h2);
    cudaGetSymbolAddress((void**)&w1r, g_w1r);
    cudaGetSymbolAddress((void**)&w2r, g_w2r);

    static cudaStream_t s2;
    static cudaEvent_t ev_feat, ev_svd;
    static int inited = 0;
    if (!inited) {
        cudaFuncSetAttribute(gemm_tf32_pipe,
                             cudaFuncAttributeMaxDynamicSharedMemorySize, 98304);
        cudaFuncSetAttribute(svd_kernel,
                             cudaFuncAttributeMaxDynamicSharedMemorySize, 70144);
        cudaStreamCreateWithFlags(&s2, cudaStreamNonBlocking);
        cudaEventCreateWithFlags(&ev_feat, cudaEventDisableTiming);
        cudaEventCreateWithFlags(&ev_svd, cudaEventDisableTiming);
        inited = 1;
    }

    // weight pre-rounding
    round_copy<<<(FEAT * 256 + 255) / 256, 256>>>(W1, w1r, FEAT * 256);
    round_copy<<<(256 * 128 + 255) / 256, 256>>>(W2, w2r, 256 * 128);

    feat_kernel<<<BATCH / 8, 256>>>(x);

    // fork: svd (writes feats[1792:1808]) runs concurrently with gemm1-main
    cudaEventRecord(ev_feat, 0);
    cudaStreamWaitEvent(s2, ev_feat, 0);
    svd_kernel<<<BATCH / 128, 128, 70144, s2>>>();

    // layer-1 main: K tiles 0..55 (k < 1792, independent of svd), raw partials
    {
        dim3 grid(2, BATCH / 128);
        gemm_tf32_pipe<<<grid, 256, 98304>>>(BATCH, 256, FEAT, FEAT, 56,
                                             feats, w1r, w1r, h1, 0, 0, 0, 0);
    }

    // join: svd must finish before the K tail (k in [1792,1808))
    cudaEventRecord(ev_svd, s2);
    cudaStreamWaitEvent(0, ev_svd, 0);

    // layer-1 tail: 1 K-tile, accumulate + bias + relu + round
    {
        dim3 grid(2, BATCH / 128);
        gemm_tf32_pipe<<<grid, 256, 98304>>>(BATCH, 256, FEAT, 16, 1,
                                             feats + 1792, w1r + (size_t)1792 * 256,
                                             b1, h1, 1, 1, 1, 1);
    }

    // layer 2: [B,256] @ [256,128] + b2, relu
    {
        dim3 grid(1, BATCH / 128);
        gemm_tf32_pipe<<<grid, 256, 98304>>>(BATCH, 128, 256, 256, 8,
                                             h1, w2r, b2, h2, 1, 0, 0, 1);
    }
    tail_kernel<<<BATCH / 256, 256>>>(W3, b3, W4, b4, out);
}